// round 8
// baseline (speedup 1.0000x reference)
#include <cuda_runtime.h>

// FusionFeature_Layer on GB300 (sm_103a), fp32 flash-attention formulation.
//
// Shapes: B=8, C=128, h=w=56, N=3136.
//   qf[b,n,c]  = query.flat [b*N*C + n*C + c]   (raw reshape -> contiguous rows)
//   sf[b,c,m]  = support.flat[b*C*N + c*N + m]
//   A = qf @ sf  (N x N), attn = softmax(A, axis=-1), mask = sigmoid(rowsum(A))
//   out_q.flat[b, n*C+c] = q.flat[...] + (attn @ qf)[n,c] * mask[n]
//   out_s.flat[b, n*C+c] = s.flat[...] * (1 + mask[n])
//
// No max-subtraction: logits ~ N(0,128), max ~45 -> exp fits fp32. Single pass
// per 64-row tile accumulating raw sums, exp sums, and unnormalized O.

namespace {
constexpr int kB  = 8;
constexpr int kC  = 128;
constexpr int kN  = 3136;   // 56*56 = 49*64
constexpr int TM  = 64;     // row tile
constexpr int TN  = 64;     // column (m) tile, 3136/64 = 49 exact
constexpr int NTH = 128;    // threads per CTA (16 tx x 8 ty)
// smem: Qs[TM][C] + Ss[C][TN] (P aliases first TM*TN) + Vs[TN][C] + 2*TM rows
constexpr int SMEM_FLOATS = TM * kC + kC * TN + TN * kC + 2 * TM;
}

__global__ __launch_bounds__(NTH, 2)
void fusion_attn_kernel(const float* __restrict__ q,
                        const float* __restrict__ s,
                        float* __restrict__ out)
{
    extern __shared__ float smem[];
    float* Qs       = smem;                 // [TM][128]  q rows (also used in epilogue)
    float* Ss       = smem + TM * kC;       // [128][TN]  support cols; P aliases [TM][TN]
    float* Vs       = Ss + kC * TN;         // [TN][128]  V = q rows of the m-tile
    float* rowscale = Vs + TN * kC;         // [TM] mask/expsum
    float* rowmask1 = rowscale + TM;        // [TM] 1+mask

    const int tid = threadIdx.x;
    const int tx  = tid & 15;               // 0..15 -> 4 cols (GEMM1) / 8 cols (GEMM2)
    const int ty  = tid >> 4;               // 0..7  -> 8 rows
    const int b   = blockIdx.y;
    const int n0  = blockIdx.x * TM;

    const float* __restrict__ qb = q + (size_t)b * (kN * kC);
    const float* __restrict__ sb = s + (size_t)b * (kN * kC);

    // ---- Load Q tile (contiguous 32KB) ----
    {
        const float4* src = reinterpret_cast<const float4*>(qb + (size_t)n0 * kC);
        float4* dst = reinterpret_cast<float4*>(Qs);
        #pragma unroll
        for (int i = 0; i < (TM * kC / 4) / NTH; i++)
            dst[tid + i * NTH] = src[tid + i * NTH];
    }

    float O[8][8];
    #pragma unroll
    for (int i = 0; i < 8; i++)
        #pragma unroll
        for (int j = 0; j < 8; j++) O[i][j] = 0.f;
    float rawP[8], expP[8];
    #pragma unroll
    for (int i = 0; i < 8; i++) { rawP[i] = 0.f; expP[i] = 0.f; }

    for (int mt = 0; mt < kN / TN; mt++) {
        const int m0 = mt * TN;

        __syncthreads();  // previous iteration's GEMM2 done reading Ss(P)/Vs

        // ---- Load S tile: Ss[c][j] = support[b, c, m0+j] ----
        #pragma unroll
        for (int i = 0; i < 16; i++) {
            int idx = tid + i * NTH;          // 0..2047
            int c   = idx >> 4;
            int j4  = (idx & 15) << 2;
            float4 v = *reinterpret_cast<const float4*>(sb + (size_t)c * kN + m0 + j4);
            *reinterpret_cast<float4*>(Ss + c * TN + j4) = v;
        }
        // ---- Load V tile (contiguous 32KB): Vs[m][c] = qf[b, m0+m, c] ----
        {
            const float4* src = reinterpret_cast<const float4*>(qb + (size_t)m0 * kC);
            float4* dst = reinterpret_cast<float4*>(Vs);
            #pragma unroll
            for (int i = 0; i < 16; i++)
                dst[tid + i * NTH] = src[tid + i * NTH];
        }
        __syncthreads();

        // ---- GEMM1: L[8][4] = Qs[rows ty*8..][128] @ Ss[128][cols tx*4..] ----
        float L[8][4];
        #pragma unroll
        for (int i = 0; i < 8; i++)
            #pragma unroll
            for (int j = 0; j < 4; j++) L[i][j] = 0.f;

        #pragma unroll 1
        for (int kb = 0; kb < kC / 4; kb++) {
            float a_[8][4], b_[4][4];
            #pragma unroll
            for (int i = 0; i < 8; i++) {
                float4 t = *reinterpret_cast<const float4*>(&Qs[(ty * 8 + i) * kC + kb * 4]);
                a_[i][0] = t.x; a_[i][1] = t.y; a_[i][2] = t.z; a_[i][3] = t.w;
            }
            #pragma unroll
            for (int u = 0; u < 4; u++) {
                float4 t = *reinterpret_cast<const float4*>(&Ss[(kb * 4 + u) * TN + tx * 4]);
                b_[u][0] = t.x; b_[u][1] = t.y; b_[u][2] = t.z; b_[u][3] = t.w;
            }
            #pragma unroll
            for (int i = 0; i < 8; i++)
                #pragma unroll
                for (int u = 0; u < 4; u++)
                    #pragma unroll
                    for (int j = 0; j < 4; j++)
                        L[i][j] += a_[i][u] * b_[u][j];
        }
        __syncthreads();  // all GEMM1 reads of Ss finished before P overwrites it

        // ---- exp + row partials; write P into Ss region (alias) ----
        #pragma unroll
        for (int i = 0; i < 8; i++) {
            rawP[i] += (L[i][0] + L[i][1]) + (L[i][2] + L[i][3]);
            float4 p;
            p.x = __expf(L[i][0]); p.y = __expf(L[i][1]);
            p.z = __expf(L[i][2]); p.w = __expf(L[i][3]);
            expP[i] += (p.x + p.y) + (p.z + p.w);
            *reinterpret_cast<float4*>(&Ss[(ty * 8 + i) * TN + tx * 4]) = p;
        }
        __syncthreads();

        // ---- GEMM2: O[8][8] += P[rows][64] @ Vs[64][cols tx*8..] ----
        #pragma unroll 1
        for (int kb = 0; kb < TN / 4; kb++) {
            float a_[8][4], b_[4][8];
            #pragma unroll
            for (int i = 0; i < 8; i++) {
                float4 t = *reinterpret_cast<const float4*>(&Ss[(ty * 8 + i) * TN + kb * 4]);
                a_[i][0] = t.x; a_[i][1] = t.y; a_[i][2] = t.z; a_[i][3] = t.w;
            }
            #pragma unroll
            for (int u = 0; u < 4; u++) {
                float4 t0 = *reinterpret_cast<const float4*>(&Vs[(kb * 4 + u) * kC + tx * 8]);
                float4 t1 = *reinterpret_cast<const float4*>(&Vs[(kb * 4 + u) * kC + tx * 8 + 4]);
                b_[u][0] = t0.x; b_[u][1] = t0.y; b_[u][2] = t0.z; b_[u][3] = t0.w;
                b_[u][4] = t1.x; b_[u][5] = t1.y; b_[u][6] = t1.z; b_[u][7] = t1.w;
            }
            #pragma unroll
            for (int i = 0; i < 8; i++)
                #pragma unroll
                for (int u = 0; u < 4; u++)
                    #pragma unroll
                    for (int j = 0; j < 8; j++)
                        O[i][j] += a_[i][u] * b_[u][j];
        }
    }

    // ---- reduce row sums across the 16 tx lanes (lanes 0-15 / 16-31 groups) ----
    #pragma unroll
    for (int i = 0; i < 8; i++) {
        float r = rawP[i], e = expP[i];
        #pragma unroll
        for (int off = 1; off < 16; off <<= 1) {
            r += __shfl_xor_sync(0xffffffffu, r, off);
            e += __shfl_xor_sync(0xffffffffu, e, off);
        }
        if (tx == 0) {
            int rr = ty * 8 + i;
            float m = 1.f / (1.f + __expf(-r));   // sigmoid of raw row sum
            rowscale[rr] = m / e;                 // mask / softmax denominator
            rowmask1[rr] = 1.f + m;
        }
    }
    __syncthreads();

    // ---- query output: out_q = q + O * scale ----
    float* outq = out + (size_t)b * (kN * kC);
    #pragma unroll
    for (int i = 0; i < 8; i++) {
        int rr = ty * 8 + i;
        float sc = rowscale[rr];
        const float* qrow = &Qs[rr * kC + tx * 8];
        float4 q0 = *reinterpret_cast<const float4*>(qrow);
        float4 q1 = *reinterpret_cast<const float4*>(qrow + 4);
        float4 o0, o1;
        o0.x = q0.x + O[i][0] * sc; o0.y = q0.y + O[i][1] * sc;
        o0.z = q0.z + O[i][2] * sc; o0.w = q0.w + O[i][3] * sc;
        o1.x = q1.x + O[i][4] * sc; o1.y = q1.y + O[i][5] * sc;
        o1.z = q1.z + O[i][6] * sc; o1.w = q1.w + O[i][7] * sc;
        float* orow = outq + (size_t)(n0 + rr) * kC + tx * 8;
        *reinterpret_cast<float4*>(orow)     = o0;
        *reinterpret_cast<float4*>(orow + 4) = o1;
    }

    // ---- support output: out_s = s * (1 + mask[row]) ----
    float* outs = out + (size_t)kB * kN * kC + (size_t)b * (kN * kC);
    {
        const float4* src = reinterpret_cast<const float4*>(sb + (size_t)n0 * kC);
        float4* dst = reinterpret_cast<float4*>(outs + (size_t)n0 * kC);
        #pragma unroll
        for (int f0 = 0; f0 < 16; f0++) {
            int f = tid + f0 * NTH;        // 0..2047, row = f/32 (32 float4 per row)
            float m1 = rowmask1[f >> 5];
            float4 v = src[f];
            v.x *= m1; v.y *= m1; v.z *= m1; v.w *= m1;
            dst[f] = v;
        }
    }
}

extern "C" void kernel_launch(void* const* d_in, const int* in_sizes, int n_in,
                              void* d_out, int out_size)
{
    const float* q = (const float*)d_in[0];   // query_feature  [8,128,56,56]
    const float* s = (const float*)d_in[1];   // support_feature[8,128,56,56]
    float* out = (float*)d_out;               // [query_out | support_out]

    const size_t smem_bytes = (size_t)SMEM_FLOATS * sizeof(float);  // ~96.5 KB
    cudaFuncSetAttribute((const void*)fusion_attn_kernel,
                         cudaFuncAttributeMaxDynamicSharedMemorySize,
                         (int)smem_bytes);

    dim3 grid(kN / TM, kB);   // 49 x 8 = 392 CTAs
    fusion_attn_kernel<<<grid, NTH, smem_bytes>>>(q, s, out);
}

// round 11
// speedup vs baseline: 2.7808x; 2.7808x over previous
#include <cuda_runtime.h>
#include <cstdint>

// FusionFeature_Layer on GB300 — emulated-fp32 flash attention on the legacy
// tensor-core path (mma.sync bf16 hi/lo split, family-generic PTX; tcgen05 is
// unavailable because the harness compiles at compute_103, not sm_103a).
//
//   qf[b,n,c] = query.flat [b*N*C + n*C + c]
//   sf[b,c,m] = support.flat[b*C*N + c*N + m]
//   A = qf @ sf ; attn = softmax(A) ; mask = sigmoid(rowsum(A))
//   out_q = q + (attn @ qf) * mask ;  out_s = s * (1 + mask)
//
// x = hi(bf16) + lo(bf16);  X*Y ~= hi*hi + hi*lo + lo*hi  (fp32 accum).
// No max-subtraction: logits <= ~45, exp fits fp32.

namespace {
constexpr int kB = 8, kC = 128, kN = 3136;   // N = 56*56 = 49*64
constexpr int TM = 64, TN = 64, NTH = 128;
constexpr int NUM_MT = kN / TN;              // 49

// smem byte offsets (all regions 8KB-aligned; 128B row pitch everywhere)
constexpr int OFF_QH  = 0;          // Q hi : 2 halves x [64 rows][64 cols] bf16
constexpr int OFF_QL  = 16384;
constexpr int OFF_SH  = 32768;      // S hi : [128 c-rows][64 m] bf16
constexpr int OFF_SL  = 49152;
constexpr int OFF_VH  = 65536;      // V hi : 2 halves x [64 m-rows][64 c] bf16
constexpr int OFF_VL  = 81920;
constexpr int OFF_ROW = 98304;      // float rowmask1[64]
constexpr int SMEM_BYTES = 98304 + 256;
}

#define SWZ(b) ((b) ^ (((b) >> 3) & 0x70))

__device__ __forceinline__ uint32_t smem_to_u32(const void* p) {
    uint32_t a;
    asm("{ .reg .u64 t; cvta.to.shared.u64 t, %1; cvt.u32.u64 %0, t; }" : "=r"(a) : "l"(p));
    return a;
}
__device__ __forceinline__ void ldsm_x4(uint32_t r[4], uint32_t addr) {
    asm volatile("ldmatrix.sync.aligned.m8n8.x4.shared.b16 {%0,%1,%2,%3}, [%4];"
                 : "=r"(r[0]), "=r"(r[1]), "=r"(r[2]), "=r"(r[3]) : "r"(addr));
}
__device__ __forceinline__ void ldsm_x4_t(uint32_t r[4], uint32_t addr) {
    asm volatile("ldmatrix.sync.aligned.m8n8.x4.trans.shared.b16 {%0,%1,%2,%3}, [%4];"
                 : "=r"(r[0]), "=r"(r[1]), "=r"(r[2]), "=r"(r[3]) : "r"(addr));
}
__device__ __forceinline__ void mma_bf16(float (&d)[4], const uint32_t (&a)[4],
                                         uint32_t b0, uint32_t b1) {
    asm volatile("mma.sync.aligned.m16n8k16.row.col.f32.bf16.bf16.f32 "
                 "{%0,%1,%2,%3}, {%4,%5,%6,%7}, {%8,%9}, {%0,%1,%2,%3};"
                 : "+f"(d[0]), "+f"(d[1]), "+f"(d[2]), "+f"(d[3])
                 : "r"(a[0]), "r"(a[1]), "r"(a[2]), "r"(a[3]), "r"(b0), "r"(b1));
}
// pack (x,y) -> bf16x2 hi (x low half) + bf16x2 lo residuals
__device__ __forceinline__ void split2(float x, float y, uint32_t& hi, uint32_t& lo) {
    asm("cvt.rn.satfinite.bf16x2.f32 %0, %1, %2;" : "=r"(hi) : "f"(y), "f"(x));
    float rx = x - __uint_as_float(hi << 16);
    float ry = y - __uint_as_float(hi & 0xFFFF0000u);
    asm("cvt.rn.satfinite.bf16x2.f32 %0, %1, %2;" : "=r"(lo) : "f"(ry), "f"(rx));
}

__global__ __launch_bounds__(NTH, 2)
void fusion_mma_kernel(const float* __restrict__ q,
                       const float* __restrict__ s,
                       float* __restrict__ out)
{
    extern __shared__ char smem[];
    const uint32_t sb = smem_to_u32(smem);
    const uint32_t sQH = sb + OFF_QH, sQL = sb + OFF_QL;
    const uint32_t sSH = sb + OFF_SH, sSL = sb + OFF_SL;
    const uint32_t sVH = sb + OFF_VH, sVL = sb + OFF_VL;
    float* rowbuf = reinterpret_cast<float*>(smem + OFF_ROW);

    const int tid  = threadIdx.x;
    const int lane = tid & 31;
    const int wid  = tid >> 5;
    const int R    = wid * 16;                 // warp's row block within the 64
    const int rowA = lane & 15;                // ldmatrix row-within-16
    const int gcol = (lane >> 4) << 4;         // ldmatrix 16B col group

    const int b  = blockIdx.y;
    const int n0 = blockIdx.x * TM;
    const float* __restrict__ qb  = q + (size_t)b * kN * kC;
    const float* __restrict__ sbp = s + (size_t)b * kN * kC;

    // ---- Convert Q tile (64 x 128 fp32) -> bf16 hi/lo, 2 column-halves ----
    #pragma unroll
    for (int i = 0; i < 16; i++) {
        int idx = tid + i * NTH;               // 0..2047 float4 slots
        int row = idx >> 5, c4 = (idx & 31) << 2;
        float4 v = *reinterpret_cast<const float4*>(qb + (size_t)(n0 + row) * kC + c4);
        uint32_t h0, l0, h1, l1;
        split2(v.x, v.y, h0, l0);
        split2(v.z, v.w, h1, l1);
        uint32_t off = ((uint32_t)(c4 >> 6) << 13) + SWZ((uint32_t)(row * 128 + (c4 & 63) * 2));
        *reinterpret_cast<uint2*>(smem + OFF_QH + off) = make_uint2(h0, h1);
        *reinterpret_cast<uint2*>(smem + OFF_QL + off) = make_uint2(l0, l1);
    }

    float oacc[16][4];
    #pragma unroll
    for (int i = 0; i < 16; i++)
        #pragma unroll
        for (int j = 0; j < 4; j++) oacc[i][j] = 0.f;
    float raw0 = 0.f, raw1 = 0.f, es0 = 0.f, es1 = 0.f;

    #pragma unroll 1
    for (int mt = 0; mt < NUM_MT; mt++) {
        const int m0 = mt * TN;
        __syncthreads();   // previous tile's ldmatrix reads complete

        // ---- S tile: [c=128 rows][m=64] bf16 hi/lo ----
        #pragma unroll
        for (int i = 0; i < 16; i++) {
            int idx = tid + i * NTH;           // 0..2047
            int c = idx >> 4, m4 = (idx & 15) << 2;
            float4 v = *reinterpret_cast<const float4*>(sbp + (size_t)c * kN + m0 + m4);
            uint32_t h0, l0, h1, l1;
            split2(v.x, v.y, h0, l0);
            split2(v.z, v.w, h1, l1);
            uint32_t sw = SWZ((uint32_t)(c * 128 + m4 * 2));
            *reinterpret_cast<uint2*>(smem + OFF_SH + sw) = make_uint2(h0, h1);
            *reinterpret_cast<uint2*>(smem + OFF_SL + sw) = make_uint2(l0, l1);
        }
        // ---- V tile: [m=64 rows][c=128] bf16 hi/lo, 2 column-halves ----
        #pragma unroll
        for (int i = 0; i < 16; i++) {
            int idx = tid + i * NTH;
            int row = idx >> 5, c4 = (idx & 31) << 2;
            float4 v = *reinterpret_cast<const float4*>(qb + (size_t)(m0 + row) * kC + c4);
            uint32_t h0, l0, h1, l1;
            split2(v.x, v.y, h0, l0);
            split2(v.z, v.w, h1, l1);
            uint32_t off = ((uint32_t)(c4 >> 6) << 13) + SWZ((uint32_t)(row * 128 + (c4 & 63) * 2));
            *reinterpret_cast<uint2*>(smem + OFF_VH + off) = make_uint2(h0, h1);
            *reinterpret_cast<uint2*>(smem + OFF_VL + off) = make_uint2(l0, l1);
        }
        __syncthreads();

        // ---- GEMM1: S(16x64 per warp) = Q(16x128) @ Sf(128x64), 3-term ----
        float sacc[8][4];
        #pragma unroll
        for (int i = 0; i < 8; i++)
            #pragma unroll
            for (int j = 0; j < 4; j++) sacc[i][j] = 0.f;

        #pragma unroll
        for (int k = 0; k < 8; k++) {
            uint32_t ah[4], al[4];
            uint32_t aoff = ((uint32_t)(k >> 2) << 13)
                          + SWZ((uint32_t)((R + rowA) * 128 + ((k & 3) << 5) + gcol));
            ldsm_x4(ah, sQH + aoff);
            ldsm_x4(al, sQL + aoff);
            uint32_t rowB128 = (uint32_t)((k * 16 + rowA) * 128);
            #pragma unroll
            for (int np = 0; np < 4; np++) {
                uint32_t bh[4], bl[4];
                uint32_t boff = SWZ(rowB128 + ((uint32_t)np << 5) + gcol);
                ldsm_x4_t(bh, sSH + boff);
                ldsm_x4_t(bl, sSL + boff);
                mma_bf16(sacc[2*np],   ah, bh[0], bh[1]);
                mma_bf16(sacc[2*np],   ah, bl[0], bl[1]);
                mma_bf16(sacc[2*np],   al, bh[0], bh[1]);
                mma_bf16(sacc[2*np+1], ah, bh[2], bh[3]);
                mma_bf16(sacc[2*np+1], ah, bl[2], bl[3]);
                mma_bf16(sacc[2*np+1], al, bh[2], bh[3]);
            }
        }

        // ---- exp + row partials; pack P directly into GEMM2 A-fragments ----
        uint32_t pah[4][4], pal[4][4];
        #pragma unroll
        for (int nt = 0; nt < 8; nt++) {
            float v0 = sacc[nt][0], v1 = sacc[nt][1], v2 = sacc[nt][2], v3 = sacc[nt][3];
            raw0 += v0 + v1;  raw1 += v2 + v3;
            float e0 = __expf(v0), e1 = __expf(v1), e2 = __expf(v2), e3 = __expf(v3);
            es0 += e0 + e1;   es1 += e2 + e3;
            int kt = nt >> 1, o = (nt & 1) << 1;
            split2(e0, e1, pah[kt][o],     pal[kt][o]);
            split2(e2, e3, pah[kt][o + 1], pal[kt][o + 1]);
        }

        // ---- GEMM2: O(16x128 per warp) += P(16x64) @ V(64x128), 3-term ----
        #pragma unroll
        for (int np = 0; np < 8; np++) {
            uint32_t vh_base = sVH + ((uint32_t)(np >> 2) << 13);
            uint32_t vl_base = sVL + ((uint32_t)(np >> 2) << 13);
            #pragma unroll
            for (int kt = 0; kt < 4; kt++) {
                uint32_t bh[4], bl[4];
                uint32_t boff = SWZ((uint32_t)((kt * 16 + rowA) * 128 + ((np & 3) << 5) + gcol));
                ldsm_x4_t(bh, vh_base + boff);
                ldsm_x4_t(bl, vl_base + boff);
                mma_bf16(oacc[2*np],   pah[kt], bh[0], bh[1]);
                mma_bf16(oacc[2*np],   pah[kt], bl[0], bl[1]);
                mma_bf16(oacc[2*np],   pal[kt], bh[0], bh[1]);
                mma_bf16(oacc[2*np+1], pah[kt], bh[2], bh[3]);
                mma_bf16(oacc[2*np+1], pah[kt], bl[2], bl[3]);
                mma_bf16(oacc[2*np+1], pal[kt], bh[2], bh[3]);
            }
        }
    }

    // ---- reduce row sums within lane quads (rows r=t/4 and r+8) ----
    #pragma unroll
    for (int off = 1; off < 4; off <<= 1) {
        raw0 += __shfl_xor_sync(0xffffffffu, raw0, off);
        raw1 += __shfl_xor_sync(0xffffffffu, raw1, off);
        es0  += __shfl_xor_sync(0xffffffffu, es0,  off);
        es1  += __shfl_xor_sync(0xffffffffu, es1,  off);
    }
    float mask0 = 1.f / (1.f + __expf(-raw0));
    float mask1 = 1.f / (1.f + __expf(-raw1));
    float sc0 = mask0 / es0, sc1 = mask1 / es1;
    if ((lane & 3) == 0) {
        rowbuf[R + (lane >> 2)]     = 1.f + mask0;
        rowbuf[R + (lane >> 2) + 8] = 1.f + mask1;
    }

    // ---- query output: out_q = q + O * scale ----
    {
        float* outq = out + (size_t)b * kN * kC;
        int gr0 = n0 + R + (lane >> 2);
        int gr1 = gr0 + 8;
        #pragma unroll
        for (int nt = 0; nt < 16; nt++) {
            int c = nt * 8 + (lane & 3) * 2;
            float2 q0 = *reinterpret_cast<const float2*>(qb + (size_t)gr0 * kC + c);
            float2 q1 = *reinterpret_cast<const float2*>(qb + (size_t)gr1 * kC + c);
            float2 o0, o1;
            o0.x = fmaf(oacc[nt][0], sc0, q0.x);
            o0.y = fmaf(oacc[nt][1], sc0, q0.y);
            o1.x = fmaf(oacc[nt][2], sc1, q1.x);
            o1.y = fmaf(oacc[nt][3], sc1, q1.y);
            *reinterpret_cast<float2*>(outq + (size_t)gr0 * kC + c) = o0;
            *reinterpret_cast<float2*>(outq + (size_t)gr1 * kC + c) = o1;
        }
    }
    __syncthreads();

    // ---- support output: out_s = s * (1 + mask[row]) ----
    {
        float* outs = out + (size_t)kB * kN * kC + (size_t)b * kN * kC;
        #pragma unroll
        for (int i = 0; i < 16; i++) {
            int idx = tid + i * NTH;               // 0..2047 float4
            int row = idx >> 5, c4 = (idx & 31) << 2;
            float m1 = rowbuf[row];
            float4 v = *reinterpret_cast<const float4*>(sbp + (size_t)(n0 + row) * kC + c4);
            v.x *= m1; v.y *= m1; v.z *= m1; v.w *= m1;
            *reinterpret_cast<float4*>(outs + (size_t)(n0 + row) * kC + c4) = v;
        }
    }
}

extern "C" void kernel_launch(void* const* d_in, const int* in_sizes, int n_in,
                              void* d_out, int out_size)
{
    const float* q = (const float*)d_in[0];   // query_feature  [8,128,56,56]
    const float* s = (const float*)d_in[1];   // support_feature[8,128,56,56]
    float* out = (float*)d_out;               // [query_out | support_out]

    cudaFuncSetAttribute((const void*)fusion_mma_kernel,
                         cudaFuncAttributeMaxDynamicSharedMemorySize, SMEM_BYTES);

    dim3 grid(kN / TM, kB);                   // 49 x 8 = 392 CTAs
    fusion_mma_kernel<<<grid, NTH, SMEM_BYTES>>>(q, s, out);
}

// round 12
// speedup vs baseline: 4.3066x; 1.5487x over previous
#include <cuda_runtime.h>
#include <cstdint>

// FusionFeature_Layer on GB300 — emulated-fp32 flash attention on mma.sync
// (bf16 hi/lo 3-term split), with a bf16-split prepass + cp.async pipelined
// tile loads. tcgen05 unavailable (harness compiles at compute_103).
//
//   qf[b,n,c] = query.flat [b*N*C + n*C + c]
//   sf[b,c,m] = support.flat[b*C*N + c*N + m]
//   A = qf @ sf ; attn = softmax(A) ; mask = sigmoid(rowsum(A))
//   out_q = q + (attn @ qf) * mask ;  out_s = s * (1 + mask)

namespace {
constexpr int kB = 8, kC = 128, kN = 3136;   // N = 56*56 = 98*32
constexpr int TM = 64, TN = 32, NTH = 128;
constexpr int NUM_MT = kN / TN;              // 98
// smem: 3 tile buffers x 32KB + rowbuf
//   buffer: S [128 c-rows][64B hi | 64B lo] (16KB) ; V: VH0,VH1,VL0,VL1
//   each [32 m-rows][64 c bf16 = 128B] (4KB) at +16K,+20K,+24K,+28K
constexpr int BUF_BYTES = 32768;
constexpr int OFF_ROW   = 3 * BUF_BYTES;     // float rowmask1[64]
constexpr int SMEM_BYTES = OFF_ROW + 256;
}

// bf16 hi/lo scratch (written by prepass)
__device__ __align__(16) uint16_t g_qh[(size_t)kB * kN * kC];
__device__ __align__(16) uint16_t g_ql[(size_t)kB * kN * kC];
__device__ __align__(16) uint16_t g_sh[(size_t)kB * kN * kC];
__device__ __align__(16) uint16_t g_sl[(size_t)kB * kN * kC];

#define SWZ(b) ((b) ^ (((b) >> 3) & 0x70))

__device__ __forceinline__ uint32_t smem_to_u32(const void* p) {
    uint32_t a;
    asm("{ .reg .u64 t; cvta.to.shared.u64 t, %1; cvt.u32.u64 %0, t; }" : "=r"(a) : "l"(p));
    return a;
}
__device__ __forceinline__ void cp16(uint32_t dst, const void* src) {
    asm volatile("cp.async.cg.shared.global [%0], [%1], 16;" :: "r"(dst), "l"(src));
}
#define CP_COMMIT() asm volatile("cp.async.commit_group;" ::: "memory")
#define CP_WAIT0()  asm volatile("cp.async.wait_group 0;" ::: "memory")
#define CP_WAIT1()  asm volatile("cp.async.wait_group 1;" ::: "memory")

__device__ __forceinline__ void ldsm_x4(uint32_t r[4], uint32_t addr) {
    asm volatile("ldmatrix.sync.aligned.m8n8.x4.shared.b16 {%0,%1,%2,%3}, [%4];"
                 : "=r"(r[0]), "=r"(r[1]), "=r"(r[2]), "=r"(r[3]) : "r"(addr));
}
__device__ __forceinline__ void ldsm_x4_t(uint32_t r[4], uint32_t addr) {
    asm volatile("ldmatrix.sync.aligned.m8n8.x4.trans.shared.b16 {%0,%1,%2,%3}, [%4];"
                 : "=r"(r[0]), "=r"(r[1]), "=r"(r[2]), "=r"(r[3]) : "r"(addr));
}
__device__ __forceinline__ void mma_bf16(float (&d)[4], const uint32_t (&a)[4],
                                         uint32_t b0, uint32_t b1) {
    asm volatile("mma.sync.aligned.m16n8k16.row.col.f32.bf16.bf16.f32 "
                 "{%0,%1,%2,%3}, {%4,%5,%6,%7}, {%8,%9}, {%0,%1,%2,%3};"
                 : "+f"(d[0]), "+f"(d[1]), "+f"(d[2]), "+f"(d[3])
                 : "r"(a[0]), "r"(a[1]), "r"(a[2]), "r"(a[3]), "r"(b0), "r"(b1));
}
// pack (x,y) -> bf16x2 hi (x in low half) + bf16x2 lo residuals
__device__ __forceinline__ void split2(float x, float y, uint32_t& hi, uint32_t& lo) {
    asm("cvt.rn.satfinite.bf16x2.f32 %0, %1, %2;" : "=r"(hi) : "f"(y), "f"(x));
    float rx = x - __uint_as_float(hi << 16);
    float ry = y - __uint_as_float(hi & 0xFFFF0000u);
    asm("cvt.rn.satfinite.bf16x2.f32 %0, %1, %2;" : "=r"(lo) : "f"(ry), "f"(rx));
}

// ---------------------------------------------------------------------------
// Prepass: fp32 -> bf16 hi/lo, layout-preserving
// ---------------------------------------------------------------------------
__global__ __launch_bounds__(256)
void prepass_kernel(const float* __restrict__ q, const float* __restrict__ s)
{
    const size_t nf4 = (size_t)kB * kN * kC / 4;
    size_t i = (size_t)blockIdx.x * blockDim.x + threadIdx.x;
    const float* src;
    uint16_t *dh, *dl;
    size_t idx;
    if (i < nf4) { src = q; dh = g_qh; dl = g_ql; idx = i; }
    else         { src = s; dh = g_sh; dl = g_sl; idx = i - nf4; }
    float4 v = reinterpret_cast<const float4*>(src)[idx];
    uint32_t h0, l0, h1, l1;
    split2(v.x, v.y, h0, l0);
    split2(v.z, v.w, h1, l1);
    reinterpret_cast<uint2*>(dh)[idx] = make_uint2(h0, h1);
    reinterpret_cast<uint2*>(dl)[idx] = make_uint2(l0, l1);
}

// ---------------------------------------------------------------------------
// Tile loader: S [128][hi64B|lo64B] + V 4 regions [32][128B], all swizzled
// ---------------------------------------------------------------------------
__device__ __forceinline__ void load_tile(uint32_t bb, int tid, int b, int m0)
{
    #pragma unroll
    for (int i = 0; i < 8; i++) {                     // S: 1024 chunks
        int idx = tid + i * NTH;
        int c = idx >> 3, j = idx & 7;
        int jj = j & 3;
        const uint16_t* src = (j < 4 ? g_sh : g_sl)
            + ((size_t)(b * kC + c) * kN + m0 + jj * 8);
        uint32_t dst = bb + SWZ((uint32_t)(c * 128 + ((j >> 2) << 6) + jj * 16));
        cp16(dst, src);
    }
    #pragma unroll
    for (int i = 0; i < 8; i++) {                     // V: 1024 chunks
        int idx = tid + i * NTH;
        int rg = idx >> 8, m = (idx >> 3) & 31, j = idx & 7;
        const uint16_t* base = (rg < 2 ? g_qh : g_ql);
        const uint16_t* src = base + ((size_t)(b * kN + m0 + m) * kC) + (rg & 1) * 64 + j * 8;
        uint32_t dst = bb + 16384 + (uint32_t)rg * 4096 + SWZ((uint32_t)(m * 128 + j * 16));
        cp16(dst, src);
    }
}

__global__ __launch_bounds__(NTH, 2)
void fusion_mma_kernel(const float* __restrict__ q,
                       const float* __restrict__ s,
                       float* __restrict__ out)
{
    extern __shared__ char smem[];
    const uint32_t sb = smem_to_u32(smem);
    float* rowbuf = reinterpret_cast<float*>(smem + OFF_ROW);

    const int tid  = threadIdx.x;
    const int lane = tid & 31;
    const int wid  = tid >> 5;
    const int R    = wid * 16;
    const int rowA = lane & 15;
    const int gcol = (lane >> 4) << 4;

    const int b  = blockIdx.y;
    const int n0 = blockIdx.x * TM;
    const float* __restrict__ qb  = q + (size_t)b * kN * kC;
    const float* __restrict__ sbp = s + (size_t)b * kN * kC;

    // ---- Stage Q tile (bf16 hi/lo from scratch) into buf0, hoist A-frags ----
    // regions: QH0@0, QH1@8192, QL0@16384, QL1@24576  (each [64 rows][128B])
    #pragma unroll
    for (int i = 0; i < 16; i++) {
        int idx = tid + i * NTH;          // 0..2047
        int hl = idx >> 10;
        int r = (idx >> 4) & 63, j = idx & 15;
        int ch = j >> 3, jj = j & 7;
        const uint16_t* base = hl ? g_ql : g_qh;
        const uint16_t* src = base + ((size_t)(b * kN + n0 + r) * kC) + ch * 64 + jj * 8;
        uint32_t dst = sb + (uint32_t)hl * 16384 + (uint32_t)ch * 8192
                     + SWZ((uint32_t)(r * 128 + jj * 16));
        cp16(dst, src);
    }
    CP_COMMIT(); CP_WAIT0(); __syncthreads();

    uint32_t qah[8][4], qal[8][4];
    #pragma unroll
    for (int k = 0; k < 8; k++) {
        uint32_t inner = SWZ((uint32_t)((R + rowA) * 128 + ((k & 3) << 5) + gcol));
        ldsm_x4(qah[k], sb + ((uint32_t)(k >> 2) << 13) + inner);
        ldsm_x4(qal[k], sb + 16384 + ((uint32_t)(k >> 2) << 13) + inner);
    }
    __syncthreads();    // Q staging area free for tile buffers

    float oacc[16][4];
    #pragma unroll
    for (int i = 0; i < 16; i++)
        #pragma unroll
        for (int j = 0; j < 4; j++) oacc[i][j] = 0.f;
    float raw0 = 0.f, raw1 = 0.f, es0 = 0.f, es1 = 0.f;

    // ---- prefetch tiles 0,1 ----
    load_tile(sb,             tid, b, 0);  CP_COMMIT();
    load_tile(sb + BUF_BYTES, tid, b, TN); CP_COMMIT();

    uint32_t bufc = sb;                       // compute buffer
    uint32_t bufp = sb + 2u * BUF_BYTES;      // prefetch target (rotates)

    #pragma unroll 1
    for (int mt = 0; mt < NUM_MT; mt++) {
        CP_WAIT1();
        __syncthreads();

        // prefetch tile mt+2 into the buffer freed by compute(mt-1)
        if (mt + 2 < NUM_MT) load_tile(bufp, tid, b, (mt + 2) * TN);
        CP_COMMIT();

        const uint32_t bb = bufc;

        // ---- GEMM1: S(16x32/warp) = Q(16x128) @ Sf(128x32), 3-term ----
        float sacc[4][4];
        #pragma unroll
        for (int i = 0; i < 4; i++)
            #pragma unroll
            for (int j = 0; j < 4; j++) sacc[i][j] = 0.f;

        #pragma unroll
        for (int k = 0; k < 8; k++) {
            uint32_t rowb = (uint32_t)((k * 16 + rowA) * 128);
            #pragma unroll
            for (int np = 0; np < 2; np++) {
                uint32_t bh[4], bl[4];
                ldsm_x4_t(bh, bb + SWZ(rowb + ((uint32_t)np << 5) + gcol));
                ldsm_x4_t(bl, bb + SWZ(rowb + 64 + ((uint32_t)np << 5) + gcol));
                mma_bf16(sacc[2*np],   qah[k], bh[0], bh[1]);
                mma_bf16(sacc[2*np],   qah[k], bl[0], bl[1]);
                mma_bf16(sacc[2*np],   qal[k], bh[0], bh[1]);
                mma_bf16(sacc[2*np+1], qah[k], bh[2], bh[3]);
                mma_bf16(sacc[2*np+1], qah[k], bl[2], bl[3]);
                mma_bf16(sacc[2*np+1], qal[k], bh[2], bh[3]);
            }
        }

        // ---- exp + row partials; pack P into GEMM2 A-fragments ----
        uint32_t pah[2][4], pal[2][4];
        #pragma unroll
        for (int nt = 0; nt < 4; nt++) {
            float v0 = sacc[nt][0], v1 = sacc[nt][1], v2 = sacc[nt][2], v3 = sacc[nt][3];
            raw0 += v0 + v1;  raw1 += v2 + v3;
            float e0 = __expf(v0), e1 = __expf(v1), e2 = __expf(v2), e3 = __expf(v3);
            es0 += e0 + e1;   es1 += e2 + e3;
            int kt = nt >> 1, o = (nt & 1) << 1;
            split2(e0, e1, pah[kt][o],     pal[kt][o]);
            split2(e2, e3, pah[kt][o + 1], pal[kt][o + 1]);
        }

        // ---- GEMM2: O(16x128/warp) += P(16x32) @ V(32x128), 3-term ----
        #pragma unroll
        for (int np = 0; np < 8; np++) {
            uint32_t vb = bb + 16384 + (((uint32_t)np >> 2) << 12);
            #pragma unroll
            for (int kt = 0; kt < 2; kt++) {
                uint32_t bh[4], bl[4];
                uint32_t off = SWZ((uint32_t)((kt * 16 + rowA) * 128 + ((np & 3) << 5) + gcol));
                ldsm_x4_t(bh, vb + off);
                ldsm_x4_t(bl, vb + 8192 + off);
                mma_bf16(oacc[2*np],   pah[kt], bh[0], bh[1]);
                mma_bf16(oacc[2*np],   pah[kt], bl[0], bl[1]);
                mma_bf16(oacc[2*np],   pal[kt], bh[0], bh[1]);
                mma_bf16(oacc[2*np+1], pah[kt], bh[2], bh[3]);
                mma_bf16(oacc[2*np+1], pah[kt], bl[2], bl[3]);
                mma_bf16(oacc[2*np+1], pal[kt], bh[2], bh[3]);
            }
        }

        // rotate buffers: compute -> next, prefetch -> just-freed
        uint32_t t = bufc;
        bufc = (bufc == sb + 2u * BUF_BYTES) ? sb : bufc + BUF_BYTES;
        bufp = (bufp == sb + 2u * BUF_BYTES) ? sb : bufp + BUF_BYTES;
        (void)t;
    }

    // ---- reduce row sums within lane quads (rows r=lane/4 and r+8) ----
    #pragma unroll
    for (int off = 1; off < 4; off <<= 1) {
        raw0 += __shfl_xor_sync(0xffffffffu, raw0, off);
        raw1 += __shfl_xor_sync(0xffffffffu, raw1, off);
        es0  += __shfl_xor_sync(0xffffffffu, es0,  off);
        es1  += __shfl_xor_sync(0xffffffffu, es1,  off);
    }
    float mask0 = 1.f / (1.f + __expf(-raw0));
    float mask1 = 1.f / (1.f + __expf(-raw1));
    float sc0 = mask0 / es0, sc1 = mask1 / es1;
    if ((lane & 3) == 0) {
        rowbuf[R + (lane >> 2)]     = 1.f + mask0;
        rowbuf[R + (lane >> 2) + 8] = 1.f + mask1;
    }

    // ---- query output: out_q = q + O * scale ----
    {
        float* outq = out + (size_t)b * kN * kC;
        int gr0 = n0 + R + (lane >> 2);
        int gr1 = gr0 + 8;
        #pragma unroll
        for (int nt = 0; nt < 16; nt++) {
            int c = nt * 8 + (lane & 3) * 2;
            float2 q0 = *reinterpret_cast<const float2*>(qb + (size_t)gr0 * kC + c);
            float2 q1 = *reinterpret_cast<const float2*>(qb + (size_t)gr1 * kC + c);
            float2 o0, o1;
            o0.x = fmaf(oacc[nt][0], sc0, q0.x);
            o0.y = fmaf(oacc[nt][1], sc0, q0.y);
            o1.x = fmaf(oacc[nt][2], sc1, q1.x);
            o1.y = fmaf(oacc[nt][3], sc1, q1.y);
            *reinterpret_cast<float2*>(outq + (size_t)gr0 * kC + c) = o0;
            *reinterpret_cast<float2*>(outq + (size_t)gr1 * kC + c) = o1;
        }
    }
    __syncthreads();

    // ---- support output: out_s = s * (1 + mask[row]) ----
    {
        float* outs = out + (size_t)kB * kN * kC + (size_t)b * kN * kC;
        #pragma unroll
        for (int i = 0; i < 16; i++) {
            int idx = tid + i * NTH;
            int row = idx >> 5, c4 = (idx & 31) << 2;
            float m1 = rowbuf[row];
            float4 v = *reinterpret_cast<const float4*>(sbp + (size_t)(n0 + row) * kC + c4);
            v.x *= m1; v.y *= m1; v.z *= m1; v.w *= m1;
            *reinterpret_cast<float4*>(outs + (size_t)(n0 + row) * kC + c4) = v;
        }
    }
}

extern "C" void kernel_launch(void* const* d_in, const int* in_sizes, int n_in,
                              void* d_out, int out_size)
{
    const float* q = (const float*)d_in[0];   // query_feature  [8,128,56,56]
    const float* s = (const float*)d_in[1];   // support_feature[8,128,56,56]
    float* out = (float*)d_out;               // [query_out | support_out]

    const size_t nf4 = (size_t)kB * kN * kC / 4;
    int pre_blocks = (int)((2 * nf4 + 255) / 256);
    prepass_kernel<<<pre_blocks, 256>>>(q, s);

    cudaFuncSetAttribute((const void*)fusion_mma_kernel,
                         cudaFuncAttributeMaxDynamicSharedMemorySize, SMEM_BYTES);
    dim3 grid(kN / TM, kB);                   // 49 x 8 = 392 CTAs
    fusion_mma_kernel<<<grid, NTH, SMEM_BYTES>>>(q, s, out);
}